// round 1
// baseline (speedup 1.0000x reference)
#include <cuda_runtime.h>
#include <math.h>

#define N_NODES 100000
#define E_EDGES 1100000
#define HID 32
#define GF 8
#define NF 8

// ---------------- persistent device scratch (no runtime allocation) ----------------
__device__ __align__(16) float d_le[E_EDGES];       // lower edge embeddings (carried across layers)
__device__ __align__(16) float d_ue[E_EDGES];       // upper edge embeddings
__device__ __align__(16) float d_ln[N_NODES * NF];  // node embeddings from lower pass (feeds upper pass)
__device__ float d_agg[N_NODES];                    // per-node edge-emb sum accumulator
__device__ float d_cntl[N_NODES];                   // per-node edge counts (lower)
__device__ float d_cntu[N_NODES];                   // per-node edge counts (upper)
__device__ float d_g[GF];                           // current global state
__device__ float d_nsum[GF];                        // sum of node embeddings (for global mean)
__device__ float d_esum;                            // sum of edge embeddings (for global mean)

__inline__ __device__ float warpAllSum(float v) {
#pragma unroll
    for (int o = 16; o > 0; o >>= 1) v += __shfl_xor_sync(0xffffffffu, v, o);
    return v;
}

// ---------------- init: zero all state (every launch must be self-contained) ----------------
__global__ void k_zero() {
    int i = blockIdx.x * blockDim.x + threadIdx.x;
    if (i < N_NODES) {
        d_agg[i] = 0.f;
        d_cntl[i] = 0.f;
        d_cntu[i] = 0.f;
    }
    if (i < GF) { d_g[i] = 0.f; d_nsum[i] = 0.f; }
    if (i == 0) d_esum = 0.f;
}

__global__ void k_count(const int* __restrict__ lrow, const int* __restrict__ urow) {
    int e = blockIdx.x * blockDim.x + threadIdx.x;
    if (e < E_EDGES) {
        atomicAdd(&d_cntl[lrow[e]], 1.0f);
        atomicAdd(&d_cntu[urow[e]], 1.0f);
    }
}

// ---------------- edge kernel: e_emb = MLP26->32->1, scatter to agg, reduce mean ----------------
template <bool HAS_SKIP, bool WRITE_OUT, bool DO_AGG>
__global__ __launch_bounds__(256) void k_edge(
    const int* __restrict__ row, const int* __restrict__ col,
    const float* __restrict__ xnode,   // N x 8
    const float* __restrict__ eprev,   // E (previous edge emb, or initial attr)
    const float* __restrict__ eskip,   // E (skip-connection attr) or unused
    const float* __restrict__ W1,      // 26 x 32
    const float* __restrict__ B1,      // 32
    const float* __restrict__ W2,      // 32
    const float* __restrict__ B2,      // 1
    float* __restrict__ ebuf,          // E output edge emb
    float* __restrict__ outp)          // final output slice (WRITE_OUT only)
{
    __shared__ __align__(16) float sW1[26 * HID];
    __shared__ float sB1[HID];
    __shared__ float sW2[HID];
    __shared__ float sg[GF];
    __shared__ float sB2;
    __shared__ float sred[8];

    int tid = threadIdx.x;
    for (int i = tid; i < 26 * HID; i += blockDim.x) sW1[i] = W1[i];
    if (tid < HID) { sB1[tid] = B1[tid]; sW2[tid] = W2[tid]; }
    if (tid < GF) sg[tid] = d_g[tid];
    if (tid == 0) sB2 = B2[0];
    __syncthreads();

    int e = blockIdx.x * blockDim.x + tid;
    float out = 0.f;
    if (e < E_EDGES) {
        float in[26];
#pragma unroll
        for (int k = 0; k < 8; k++) in[k] = sg[k];
        int r = row[e], c = col[e];
        const float4* xr = reinterpret_cast<const float4*>(xnode + (size_t)r * 8);
        const float4* xc = reinterpret_cast<const float4*>(xnode + (size_t)c * 8);
        float4 a0 = xr[0], a1 = xr[1], c0 = xc[0], c1 = xc[1];
        in[8] = a0.x;  in[9] = a0.y;  in[10] = a0.z; in[11] = a0.w;
        in[12] = a1.x; in[13] = a1.y; in[14] = a1.z; in[15] = a1.w;
        in[16] = c0.x; in[17] = c0.y; in[18] = c0.z; in[19] = c0.w;
        in[20] = c1.x; in[21] = c1.y; in[22] = c1.z; in[23] = c1.w;
        in[24] = eprev[e];
        in[25] = HAS_SKIP ? eskip[e] : 0.f;

        float h[HID];
#pragma unroll
        for (int j = 0; j < HID; j++) h[j] = sB1[j];
#pragma unroll
        for (int k = 0; k < 26; k++) {
            float v = in[k];
            const float4* wr = reinterpret_cast<const float4*>(&sW1[k * HID]);
#pragma unroll
            for (int j4 = 0; j4 < HID / 4; j4++) {
                float4 w = wr[j4];
                h[j4 * 4 + 0] = fmaf(v, w.x, h[j4 * 4 + 0]);
                h[j4 * 4 + 1] = fmaf(v, w.y, h[j4 * 4 + 1]);
                h[j4 * 4 + 2] = fmaf(v, w.z, h[j4 * 4 + 2]);
                h[j4 * 4 + 3] = fmaf(v, w.w, h[j4 * 4 + 3]);
            }
        }
        out = sB2;
#pragma unroll
        for (int j = 0; j < HID; j++) out = fmaf(fmaxf(h[j], 0.f), sW2[j], out);

        ebuf[e] = out;
        if (DO_AGG) atomicAdd(&d_agg[r], out);
        if (WRITE_OUT) outp[e] = (r == c) ? expf(out) : out;
    }

    if (DO_AGG) {
        float s = warpAllSum(out);
        if ((tid & 31) == 0) sred[tid >> 5] = s;
        __syncthreads();
        if (tid < 8) {
            float v = sred[tid];
            v += __shfl_xor_sync(0xffu, v, 1);
            v += __shfl_xor_sync(0xffu, v, 2);
            v += __shfl_xor_sync(0xffu, v, 4);
            if (tid == 0) atomicAdd(&d_esum, v);
        }
    }
}

// ---------------- node kernel: n_emb = MLP17->32->8; zeros agg after read ----------------
template <bool STORE>
__global__ __launch_bounds__(256) void k_node(
    const float* __restrict__ xnode,   // N x 8
    const float* __restrict__ cnt,     // N
    const float* __restrict__ W1,      // 17 x 32
    const float* __restrict__ B1,      // 32
    const float* __restrict__ W2,      // 32 x 8
    const float* __restrict__ B2)      // 8
{
    __shared__ __align__(16) float sW1[17 * HID];
    __shared__ __align__(16) float sW2[HID * NF];
    __shared__ float sB1[HID];
    __shared__ float sB2[NF];
    __shared__ float sg[GF];
    __shared__ float sred[8][NF];

    int tid = threadIdx.x;
    for (int i = tid; i < 17 * HID; i += blockDim.x) sW1[i] = W1[i];
    for (int i = tid; i < HID * NF; i += blockDim.x) sW2[i] = W2[i];
    if (tid < HID) sB1[tid] = B1[tid];
    if (tid < NF) { sB2[tid] = B2[tid]; sg[tid] = d_g[tid]; }
    __syncthreads();

    int v = blockIdx.x * blockDim.x + tid;
    float o[NF];
#pragma unroll
    for (int f = 0; f < NF; f++) o[f] = 0.f;

    if (v < N_NODES) {
        float in[17];
#pragma unroll
        for (int k = 0; k < 8; k++) in[k] = sg[k];
        const float4* xp = reinterpret_cast<const float4*>(xnode + (size_t)v * 8);
        float4 x0 = xp[0], x1 = xp[1];
        in[8] = x0.x;  in[9] = x0.y;  in[10] = x0.z; in[11] = x0.w;
        in[12] = x1.x; in[13] = x1.y; in[14] = x1.z; in[15] = x1.w;
        in[16] = d_agg[v] / fmaxf(cnt[v], 1.0f);
        d_agg[v] = 0.f;  // recycle for next pass

        float h[HID];
#pragma unroll
        for (int j = 0; j < HID; j++) h[j] = sB1[j];
#pragma unroll
        for (int k = 0; k < 17; k++) {
            float val = in[k];
            const float4* wr = reinterpret_cast<const float4*>(&sW1[k * HID]);
#pragma unroll
            for (int j4 = 0; j4 < HID / 4; j4++) {
                float4 w = wr[j4];
                h[j4 * 4 + 0] = fmaf(val, w.x, h[j4 * 4 + 0]);
                h[j4 * 4 + 1] = fmaf(val, w.y, h[j4 * 4 + 1]);
                h[j4 * 4 + 2] = fmaf(val, w.z, h[j4 * 4 + 2]);
                h[j4 * 4 + 3] = fmaf(val, w.w, h[j4 * 4 + 3]);
            }
        }
#pragma unroll
        for (int f = 0; f < NF; f++) o[f] = sB2[f];
#pragma unroll
        for (int j = 0; j < HID; j++) {
            float r = fmaxf(h[j], 0.f);
            const float4* wr = reinterpret_cast<const float4*>(&sW2[j * NF]);
            float4 w0 = wr[0], w1 = wr[1];
            o[0] = fmaf(r, w0.x, o[0]); o[1] = fmaf(r, w0.y, o[1]);
            o[2] = fmaf(r, w0.z, o[2]); o[3] = fmaf(r, w0.w, o[3]);
            o[4] = fmaf(r, w1.x, o[4]); o[5] = fmaf(r, w1.y, o[5]);
            o[6] = fmaf(r, w1.z, o[6]); o[7] = fmaf(r, w1.w, o[7]);
        }
        if (STORE) {
            float4* dst = reinterpret_cast<float4*>(&d_ln[(size_t)v * 8]);
            dst[0] = make_float4(o[0], o[1], o[2], o[3]);
            dst[1] = make_float4(o[4], o[5], o[6], o[7]);
        }
    }

    // block-reduce the 8 feature sums for the global mean
#pragma unroll
    for (int f = 0; f < NF; f++) {
        float s = warpAllSum(o[f]);
        if ((tid & 31) == 0) sred[tid >> 5][f] = s;
    }
    __syncthreads();
    if (tid < NF) {
        float s = 0.f;
#pragma unroll
        for (int w = 0; w < 8; w++) s += sred[w][tid];
        atomicAdd(&d_nsum[tid], s);
    }
}

// ---------------- global kernel: g = MLP17->32->8 on means; recycles accumulators ----------------
__global__ void k_global(const float* __restrict__ W1, const float* __restrict__ B1,
                         const float* __restrict__ W2, const float* __restrict__ B2)
{
    int j = threadIdx.x;  // 0..31
    float in[17];
#pragma unroll
    for (int f = 0; f < NF; f++) in[f] = d_nsum[f] / (float)N_NODES;
    in[8] = d_esum / (float)E_EDGES;
#pragma unroll
    for (int f = 0; f < GF; f++) in[9 + f] = d_g[f];

    float h = B1[j];
#pragma unroll
    for (int k = 0; k < 17; k++) h = fmaf(in[k], W1[k * HID + j], h);
    h = fmaxf(h, 0.f);

    float gn[GF];
#pragma unroll
    for (int f = 0; f < GF; f++) gn[f] = warpAllSum(h * W2[j * NF + f]);

    if (j < GF) {
        d_g[j] = B2[j] + gn[j];
        d_nsum[j] = 0.f;
    }
    if (j == 0) d_esum = 0.f;
}

// ---------------- host launch ----------------
extern "C" void kernel_launch(void* const* d_in, const int* in_sizes, int n_in,
                              void* d_out, int out_size)
{
    const float* x     = (const float*)d_in[0];
    const int*   lei   = (const int*)d_in[1];
    const int*   uei   = (const int*)d_in[2];
    const float* lattr = (const float*)d_in[3];
    const float* uattr = (const float*)d_in[4];
    const float* eW1 = (const float*)d_in[5];
    const float* eb1 = (const float*)d_in[6];
    const float* eW2 = (const float*)d_in[7];
    const float* eb2 = (const float*)d_in[8];
    const float* nW1 = (const float*)d_in[9];
    const float* nb1 = (const float*)d_in[10];
    const float* nW2 = (const float*)d_in[11];
    const float* gW1 = (const float*)d_in[13];
    const float* gb1 = (const float*)d_in[14];
    const float* gW2 = (const float*)d_in[15];
    const float* gb2 = (const float*)d_in[16];
    const float* nb2 = (const float*)d_in[12];
    float* outp = (float*)d_out;

    const int* lrow = lei;
    const int* lcol = lei + E_EDGES;
    const int* urow = uei;
    const int* ucol = uei + E_EDGES;

    float *p_le, *p_ue, *p_ln, *p_cntl, *p_cntu;
    cudaGetSymbolAddress((void**)&p_le, d_le);
    cudaGetSymbolAddress((void**)&p_ue, d_ue);
    cudaGetSymbolAddress((void**)&p_ln, d_ln);
    cudaGetSymbolAddress((void**)&p_cntl, d_cntl);
    cudaGetSymbolAddress((void**)&p_cntu, d_cntu);

    const int EB = (E_EDGES + 255) / 256;
    const int NB = (N_NODES + 255) / 256;

    k_zero<<<NB, 256>>>();
    k_count<<<EB, 256>>>(lrow, urow);

    // weight slice helpers: (block b, layer i) -> offset (b*3 + i)
#define EW(b, i) eW1 + (size_t)((b)*3 + (i)) * 26 * HID, eb1 + ((b)*3 + (i)) * HID, \
                 eW2 + ((b)*3 + (i)) * HID, eb2 + ((b)*3 + (i))
#define NW(b, i) nW1 + (size_t)((b)*3 + (i)) * 17 * HID, nb1 + ((b)*3 + (i)) * HID, \
                 nW2 + (size_t)((b)*3 + (i)) * HID * NF, nb2 + ((b)*3 + (i)) * NF
#define GW(b, i) gW1 + (size_t)((b)*3 + (i)) * 17 * HID, gb1 + ((b)*3 + (i)) * HID, \
                 gW2 + (size_t)((b)*3 + (i)) * HID * NF, gb2 + ((b)*3 + (i)) * NF

    // ---- layer 0 ----
    k_edge<false, false, true><<<EB, 256>>>(lrow, lcol, x, lattr, lattr, EW(0, 0), p_le, outp);
    k_node<true><<<NB, 256>>>(x, p_cntl, NW(0, 0));
    k_global<<<1, 32>>>(GW(0, 0));
    k_edge<false, false, true><<<EB, 256>>>(urow, ucol, p_ln, uattr, uattr, EW(1, 0), p_ue, outp);
    k_node<false><<<NB, 256>>>(p_ln, p_cntu, NW(1, 0));
    k_global<<<1, 32>>>(GW(1, 0));

    // ---- layer 1 ----
    k_edge<true, false, true><<<EB, 256>>>(lrow, lcol, x, p_le, lattr, EW(0, 1), p_le, outp);
    k_node<true><<<NB, 256>>>(x, p_cntl, NW(0, 1));
    k_global<<<1, 32>>>(GW(0, 1));
    k_edge<false, false, true><<<EB, 256>>>(urow, ucol, p_ln, p_ue, uattr, EW(1, 1), p_ue, outp);
    k_node<false><<<NB, 256>>>(p_ln, p_cntu, NW(1, 1));
    k_global<<<1, 32>>>(GW(1, 1));

    // ---- layer 2 (writes final output; upper pass skips unused node/global work) ----
    k_edge<true, true, true><<<EB, 256>>>(lrow, lcol, x, p_le, lattr, EW(0, 2), p_le, outp);
    k_node<true><<<NB, 256>>>(x, p_cntl, NW(0, 2));
    k_global<<<1, 32>>>(GW(0, 2));
    k_edge<false, true, false><<<EB, 256>>>(urow, ucol, p_ln, p_ue, uattr, EW(1, 2), p_ue,
                                            outp + E_EDGES);

#undef EW
#undef NW
#undef GW
}

// round 3
// speedup vs baseline: 1.2742x; 1.2742x over previous
#include <cuda_runtime.h>
#include <math.h>

#define N_NODES 100000
#define E_EDGES 1100000
#define HID 32
#define GF 8
#define NF 8

// ---------------- persistent device scratch ----------------
__device__ __align__(16) float d_hrc_l[(size_t)N_NODES * 64]; // per-node precomputed h rows (lower): [hr(32) | hc(32)]
__device__ __align__(16) float d_hrc_u[(size_t)N_NODES * 64]; // same for upper pass
__device__ __align__(16) float d_le[E_EDGES];
__device__ __align__(16) float d_ue[E_EDGES];
__device__ __align__(16) float d_ln[N_NODES * NF];
__device__ float d_agg[N_NODES];
__device__ float d_cntl[N_NODES];
__device__ float d_cntu[N_NODES];
__device__ float d_g[GF];
__device__ float d_nsum[GF];
__device__ float d_esum;
__device__ float d_hbase_e[HID];  // eb1 + g @ eW1[0:8]  (for the NEXT edge pass)
__device__ float d_hbase_n[HID];  // nb1 + g @ nW1[0:8]  (for the NEXT node pass)

__inline__ __device__ float warpAllSum(float v) {
#pragma unroll
    for (int o = 16; o > 0; o >>= 1) v += __shfl_xor_sync(0xffffffffu, v, o);
    return v;
}

// ---------------- init ----------------
__global__ void k_zero(const float* __restrict__ eb1_0, const float* __restrict__ nb1_0) {
    int i = blockIdx.x * blockDim.x + threadIdx.x;
    if (i < N_NODES) {
        d_agg[i] = 0.f;
        d_cntl[i] = 0.f;
        d_cntu[i] = 0.f;
    }
    if (blockIdx.x == 0) {
        int j = threadIdx.x;
        if (j < HID) {  // g = 0 initially -> bases are just the biases
            d_hbase_e[j] = eb1_0[j];
            d_hbase_n[j] = nb1_0[j];
        }
        if (j < GF) { d_g[j] = 0.f; d_nsum[j] = 0.f; }
        if (j == 0) d_esum = 0.f;
    }
}

__global__ void k_count(const int* __restrict__ lrow, const int* __restrict__ urow) {
    int e = blockIdx.x * blockDim.x + threadIdx.x;
    if (e < E_EDGES) {
        atomicAdd(&d_cntl[lrow[e]], 1.0f);
        atomicAdd(&d_cntu[urow[e]], 1.0f);
    }
}

// ---------------- per-node precompute: hr = x @ W1[8:16], hc = x @ W1[16:24] ----------------
__global__ __launch_bounds__(256) void k_prep(const float* __restrict__ xn,
                                              const float* __restrict__ W1,
                                              float* __restrict__ hrc) {
    __shared__ __align__(16) float sW[16 * HID];
    int tid = threadIdx.x;
    for (int i = tid; i < 16 * HID; i += 256) sW[i] = W1[8 * HID + i];
    __syncthreads();

    int v = blockIdx.x * 256 + tid;
    if (v >= N_NODES) return;
    const float4* xp = reinterpret_cast<const float4*>(xn + (size_t)v * 8);
    float4 x0 = xp[0], x1 = xp[1];
    float xv[8] = {x0.x, x0.y, x0.z, x0.w, x1.x, x1.y, x1.z, x1.w};

    float h[HID];
    float4* dst = reinterpret_cast<float4*>(hrc + (size_t)v * 64);
#pragma unroll
    for (int half = 0; half < 2; half++) {
#pragma unroll
        for (int j = 0; j < HID; j++) h[j] = 0.f;
#pragma unroll
        for (int k = 0; k < 8; k++) {
            float val = xv[k];
            const float4* wr = reinterpret_cast<const float4*>(&sW[(half * 8 + k) * HID]);
#pragma unroll
            for (int j4 = 0; j4 < HID / 4; j4++) {
                float4 w = wr[j4];
                h[j4 * 4 + 0] = fmaf(val, w.x, h[j4 * 4 + 0]);
                h[j4 * 4 + 1] = fmaf(val, w.y, h[j4 * 4 + 1]);
                h[j4 * 4 + 2] = fmaf(val, w.z, h[j4 * 4 + 2]);
                h[j4 * 4 + 3] = fmaf(val, w.w, h[j4 * 4 + 3]);
            }
        }
#pragma unroll
        for (int j4 = 0; j4 < HID / 4; j4++)
            dst[half * 8 + j4] = make_float4(h[j4 * 4], h[j4 * 4 + 1], h[j4 * 4 + 2], h[j4 * 4 + 3]);
    }
}

// ---------------- edge kernel: 8 lanes per edge, table-gather formulation ----------------
template <bool HAS_SKIP, bool WRITE_OUT, bool DO_AGG>
__global__ __launch_bounds__(256) void k_edge(
    const int* __restrict__ row, const int* __restrict__ col,
    const float* __restrict__ eprev, const float* __restrict__ eskip,
    const float* __restrict__ W1,   // full 26x32 (rows 24,25 used)
    const float* __restrict__ W2,   // 32
    const float* __restrict__ B2,   // 1
    const float* __restrict__ hrc,  // N x 64 table
    float* __restrict__ ebuf,
    float* __restrict__ outp) {
    __shared__ float sred[8];
    int tid = threadIdx.x;
    int c = tid & 7;  // component group: owns h[c*4 .. c*4+3]

    float base[4], w24[4], w25[4], w2[4];
#pragma unroll
    for (int i = 0; i < 4; i++) {
        base[i] = d_hbase_e[c * 4 + i];
        w24[i] = __ldg(&W1[24 * HID + c * 4 + i]);
        w25[i] = HAS_SKIP ? __ldg(&W1[25 * HID + c * 4 + i]) : 0.f;
        w2[i] = __ldg(&W2[c * 4 + i]);
    }
    float b2 = __ldg(B2);

    float esum_local = 0.f;
    for (int e = blockIdx.x * 32 + (tid >> 3); e < E_EDGES; e += gridDim.x * 32) {
        int r = row[e], cl = col[e];
        float ep = eprev[e];
        float es = HAS_SKIP ? eskip[e] : 0.f;
        float4 hr = *reinterpret_cast<const float4*>(&hrc[(size_t)r * 64 + c * 4]);
        float4 hc = *reinterpret_cast<const float4*>(&hrc[(size_t)cl * 64 + 32 + c * 4]);

        float p = 0.f;
        {
            float t;
            t = base[0] + hr.x + hc.x; t = fmaf(ep, w24[0], t); if (HAS_SKIP) t = fmaf(es, w25[0], t);
            p = fmaf(fmaxf(t, 0.f), w2[0], p);
            t = base[1] + hr.y + hc.y; t = fmaf(ep, w24[1], t); if (HAS_SKIP) t = fmaf(es, w25[1], t);
            p = fmaf(fmaxf(t, 0.f), w2[1], p);
            t = base[2] + hr.z + hc.z; t = fmaf(ep, w24[2], t); if (HAS_SKIP) t = fmaf(es, w25[2], t);
            p = fmaf(fmaxf(t, 0.f), w2[2], p);
            t = base[3] + hr.w + hc.w; t = fmaf(ep, w24[3], t); if (HAS_SKIP) t = fmaf(es, w25[3], t);
            p = fmaf(fmaxf(t, 0.f), w2[3], p);
        }
        // reduce across the 8 lanes of this edge group
        p += __shfl_down_sync(0xffffffffu, p, 4);
        p += __shfl_down_sync(0xffffffffu, p, 2);
        p += __shfl_down_sync(0xffffffffu, p, 1);
        if (c == 0) {
            float out = p + b2;
            ebuf[e] = out;
            if (DO_AGG) {
                atomicAdd(&d_agg[r], out);
                esum_local += out;
            }
            if (WRITE_OUT) outp[e] = (r == cl) ? expf(out) : out;
        }
    }

    if (DO_AGG) {
        float s = warpAllSum(esum_local);
        if ((tid & 31) == 0) sred[tid >> 5] = s;
        __syncthreads();
        if (tid < 8) {
            float v = sred[tid];
            v += __shfl_xor_sync(0xffu, v, 1);
            v += __shfl_xor_sync(0xffu, v, 2);
            v += __shfl_xor_sync(0xffu, v, 4);
            if (tid == 0) atomicAdd(&d_esum, v);
        }
    }
}

// ---------------- node kernel (g folded into d_hbase_n); lower variant fuses hrc_u build ----------------
template <bool FUSE_U>
__global__ __launch_bounds__(256) void k_node(
    const float* __restrict__ xn,   // N x 8 (x or ln)
    const float* __restrict__ cnt,  // N
    const float* __restrict__ W1,   // 17 x 32 (rows 8..16 used)
    const float* __restrict__ W2,   // 32 x 8
    const float* __restrict__ B2,   // 8
    const float* __restrict__ uW1)  // next (upper) edge W1, rows 8..24, used if FUSE_U
{
    __shared__ __align__(16) float sW1[9 * HID];   // x rows (8) + agg row (1)
    __shared__ __align__(16) float sW2[HID * NF];
    __shared__ __align__(16) float sUW[16 * HID];
    __shared__ float sB2[NF];
    __shared__ float sbase[HID];
    __shared__ float sred[8][NF];

    int tid = threadIdx.x;
    for (int i = tid; i < 9 * HID; i += 256) sW1[i] = W1[8 * HID + i];
    for (int i = tid; i < HID * NF; i += 256) sW2[i] = W2[i];
    if (FUSE_U)
        for (int i = tid; i < 16 * HID; i += 256) sUW[i] = uW1[8 * HID + i];
    if (tid < HID) sbase[tid] = d_hbase_n[tid];
    if (tid < NF) sB2[tid] = B2[tid];
    __syncthreads();

    int v = blockIdx.x * 256 + tid;
    float o[NF];
#pragma unroll
    for (int f = 0; f < NF; f++) o[f] = 0.f;

    if (v < N_NODES) {
        const float4* xp = reinterpret_cast<const float4*>(xn + (size_t)v * 8);
        float4 x0 = xp[0], x1 = xp[1];
        float xv[8] = {x0.x, x0.y, x0.z, x0.w, x1.x, x1.y, x1.z, x1.w};
        float a = d_agg[v] / fmaxf(cnt[v], 1.0f);
        d_agg[v] = 0.f;  // recycle for next pass

        float h[HID];
#pragma unroll
        for (int j = 0; j < HID; j++) h[j] = sbase[j];
#pragma unroll
        for (int k = 0; k < 9; k++) {
            float val = (k < 8) ? xv[k] : a;
            const float4* wr = reinterpret_cast<const float4*>(&sW1[k * HID]);
#pragma unroll
            for (int j4 = 0; j4 < HID / 4; j4++) {
                float4 w = wr[j4];
                h[j4 * 4 + 0] = fmaf(val, w.x, h[j4 * 4 + 0]);
                h[j4 * 4 + 1] = fmaf(val, w.y, h[j4 * 4 + 1]);
                h[j4 * 4 + 2] = fmaf(val, w.z, h[j4 * 4 + 2]);
                h[j4 * 4 + 3] = fmaf(val, w.w, h[j4 * 4 + 3]);
            }
        }
#pragma unroll
        for (int f = 0; f < NF; f++) o[f] = sB2[f];
#pragma unroll
        for (int j = 0; j < HID; j++) {
            float r = fmaxf(h[j], 0.f);
            const float4* wr = reinterpret_cast<const float4*>(&sW2[j * NF]);
            float4 w0 = wr[0], w1 = wr[1];
            o[0] = fmaf(r, w0.x, o[0]); o[1] = fmaf(r, w0.y, o[1]);
            o[2] = fmaf(r, w0.z, o[2]); o[3] = fmaf(r, w0.w, o[3]);
            o[4] = fmaf(r, w1.x, o[4]); o[5] = fmaf(r, w1.y, o[5]);
            o[6] = fmaf(r, w1.z, o[6]); o[7] = fmaf(r, w1.w, o[7]);
        }

        if (FUSE_U) {
            float4* lnp = reinterpret_cast<float4*>(&d_ln[(size_t)v * 8]);
            lnp[0] = make_float4(o[0], o[1], o[2], o[3]);
            lnp[1] = make_float4(o[4], o[5], o[6], o[7]);
            // build next-pass (upper edge) table from in-register output
            float4* dst = reinterpret_cast<float4*>(&d_hrc_u[(size_t)v * 64]);
#pragma unroll
            for (int half = 0; half < 2; half++) {
                float t[HID];
#pragma unroll
                for (int j = 0; j < HID; j++) t[j] = 0.f;
#pragma unroll
                for (int k = 0; k < 8; k++) {
                    float val = o[k];
                    const float4* wr = reinterpret_cast<const float4*>(&sUW[(half * 8 + k) * HID]);
#pragma unroll
                    for (int j4 = 0; j4 < HID / 4; j4++) {
                        float4 w = wr[j4];
                        t[j4 * 4 + 0] = fmaf(val, w.x, t[j4 * 4 + 0]);
                        t[j4 * 4 + 1] = fmaf(val, w.y, t[j4 * 4 + 1]);
                        t[j4 * 4 + 2] = fmaf(val, w.z, t[j4 * 4 + 2]);
                        t[j4 * 4 + 3] = fmaf(val, w.w, t[j4 * 4 + 3]);
                    }
                }
#pragma unroll
                for (int j4 = 0; j4 < HID / 4; j4++)
                    dst[half * 8 + j4] = make_float4(t[j4 * 4], t[j4 * 4 + 1], t[j4 * 4 + 2], t[j4 * 4 + 3]);
            }
        }
    }

#pragma unroll
    for (int f = 0; f < NF; f++) {
        float s = warpAllSum(o[f]);
        if ((tid & 31) == 0) sred[tid >> 5][f] = s;
    }
    __syncthreads();
    if (tid < NF) {
        float s = 0.f;
#pragma unroll
        for (int w = 0; w < 8; w++) s += sred[w][tid];
        atomicAdd(&d_nsum[tid], s);
    }
}

// ---------------- global kernel: g update + precompute next-pass biases ----------------
__global__ void k_global(const float* __restrict__ W1, const float* __restrict__ B1,
                         const float* __restrict__ W2, const float* __restrict__ B2,
                         const float* __restrict__ neW1, const float* __restrict__ neB1,
                         const float* __restrict__ nnW1, const float* __restrict__ nnB1) {
    int j = threadIdx.x;  // 0..31
    float in[17];
#pragma unroll
    for (int f = 0; f < NF; f++) in[f] = d_nsum[f] / (float)N_NODES;
    in[8] = d_esum / (float)E_EDGES;
#pragma unroll
    for (int f = 0; f < GF; f++) in[9 + f] = d_g[f];

    float h = B1[j];
#pragma unroll
    for (int k = 0; k < 17; k++) h = fmaf(in[k], W1[k * HID + j], h);
    h = fmaxf(h, 0.f);

    // new g (ALL lanes): g_new[f] = B2[f] + sum_j relu(h_j) * W2[j][f]
    float gnew[GF];
#pragma unroll
    for (int f = 0; f < GF; f++) gnew[f] = __ldg(&B2[f]) + warpAllSum(h * W2[j * NF + f]);

    // fold new g into next-pass layer-1 biases
    float be = neB1[j], bn = nnB1[j];
#pragma unroll
    for (int f = 0; f < GF; f++) {
        be = fmaf(gnew[f], neW1[f * HID + j], be);
        bn = fmaf(gnew[f], nnW1[f * HID + j], bn);
    }
    d_hbase_e[j] = be;
    d_hbase_n[j] = bn;

    if (j < GF) {
        d_g[j] = gnew[j];
        d_nsum[j] = 0.f;
    }
    if (j == 0) d_esum = 0.f;
}

// ---------------- host launch ----------------
extern "C" void kernel_launch(void* const* d_in, const int* in_sizes, int n_in,
                              void* d_out, int out_size) {
    const float* x = (const float*)d_in[0];
    const int* lei = (const int*)d_in[1];
    const int* uei = (const int*)d_in[2];
    const float* lattr = (const float*)d_in[3];
    const float* uattr = (const float*)d_in[4];
    const float* eW1 = (const float*)d_in[5];
    const float* eb1 = (const float*)d_in[6];
    const float* eW2 = (const float*)d_in[7];
    const float* eb2 = (const float*)d_in[8];
    const float* nW1 = (const float*)d_in[9];
    const float* nb1 = (const float*)d_in[10];
    const float* nW2 = (const float*)d_in[11];
    const float* nb2 = (const float*)d_in[12];
    const float* gW1 = (const float*)d_in[13];
    const float* gb1 = (const float*)d_in[14];
    const float* gW2 = (const float*)d_in[15];
    const float* gb2 = (const float*)d_in[16];
    float* outp = (float*)d_out;

    const int* lrow = lei;
    const int* lcol = lei + E_EDGES;
    const int* urow = uei;
    const int* ucol = uei + E_EDGES;

    float *p_le, *p_ue, *p_ln, *p_cntl, *p_cntu, *p_hl, *p_hu;
    cudaGetSymbolAddress((void**)&p_le, d_le);
    cudaGetSymbolAddress((void**)&p_ue, d_ue);
    cudaGetSymbolAddress((void**)&p_ln, d_ln);
    cudaGetSymbolAddress((void**)&p_cntl, d_cntl);
    cudaGetSymbolAddress((void**)&p_cntu, d_cntu);
    cudaGetSymbolAddress((void**)&p_hl, d_hrc_l);
    cudaGetSymbolAddress((void**)&p_hu, d_hrc_u);

    const int EB = (E_EDGES + 255) / 256;
    const int NB = (N_NODES + 255) / 256;
    const int EGB = 1184;  // grid-stride blocks for k_edge (8 per SM)

    // weight slice helpers: (block b, layer i) -> flat index (b*3 + i)
#define EW1P(b, i) (eW1 + (size_t)((b)*3 + (i)) * 26 * HID)
#define EB1P(b, i) (eb1 + ((b)*3 + (i)) * HID)
#define EW2P(b, i) (eW2 + ((b)*3 + (i)) * HID)
#define EB2P(b, i) (eb2 + ((b)*3 + (i)))
#define NW1P(b, i) (nW1 + (size_t)((b)*3 + (i)) * 17 * HID)
#define NB1P(b, i) (nb1 + ((b)*3 + (i)) * HID)
#define NW2P(b, i) (nW2 + (size_t)((b)*3 + (i)) * HID * NF)
#define NB2P(b, i) (nb2 + ((b)*3 + (i)) * NF)
#define GW(b, i) gW1 + (size_t)((b)*3 + (i)) * 17 * HID, gb1 + ((b)*3 + (i)) * HID, \
                 gW2 + (size_t)((b)*3 + (i)) * HID * NF, gb2 + ((b)*3 + (i)) * NF

    k_zero<<<NB, 256>>>(EB1P(0, 0), NB1P(0, 0));
    k_count<<<EB, 256>>>(lrow, urow);

    // ---- layer 0 ----
    k_prep<<<NB, 256>>>(x, EW1P(0, 0), p_hl);
    k_edge<false, false, true><<<EGB, 256>>>(lrow, lcol, lattr, lattr, EW1P(0, 0), EW2P(0, 0), EB2P(0, 0), p_hl, p_le, outp);
    k_node<true><<<NB, 256>>>(x, p_cntl, NW1P(0, 0), NW2P(0, 0), NB2P(0, 0), EW1P(1, 0));
    k_global<<<1, 32>>>(GW(0, 0), EW1P(1, 0), EB1P(1, 0), NW1P(1, 0), NB1P(1, 0));
    k_edge<false, false, true><<<EGB, 256>>>(urow, ucol, uattr, uattr, EW1P(1, 0), EW2P(1, 0), EB2P(1, 0), p_hu, p_ue, outp);
    k_node<false><<<NB, 256>>>(p_ln, p_cntu, NW1P(1, 0), NW2P(1, 0), NB2P(1, 0), EW1P(1, 0));
    k_global<<<1, 32>>>(GW(1, 0), EW1P(0, 1), EB1P(0, 1), NW1P(0, 1), NB1P(0, 1));

    // ---- layer 1 ----
    k_prep<<<NB, 256>>>(x, EW1P(0, 1), p_hl);
    k_edge<true, false, true><<<EGB, 256>>>(lrow, lcol, p_le, lattr, EW1P(0, 1), EW2P(0, 1), EB2P(0, 1), p_hl, p_le, outp);
    k_node<true><<<NB, 256>>>(x, p_cntl, NW1P(0, 1), NW2P(0, 1), NB2P(0, 1), EW1P(1, 1));
    k_global<<<1, 32>>>(GW(0, 1), EW1P(1, 1), EB1P(1, 1), NW1P(1, 1), NB1P(1, 1));
    k_edge<false, false, true><<<EGB, 256>>>(urow, ucol, p_ue, uattr, EW1P(1, 1), EW2P(1, 1), EB2P(1, 1), p_hu, p_ue, outp);
    k_node<false><<<NB, 256>>>(p_ln, p_cntu, NW1P(1, 1), NW2P(1, 1), NB2P(1, 1), EW1P(1, 1));
    k_global<<<1, 32>>>(GW(1, 1), EW1P(0, 2), EB1P(0, 2), NW1P(0, 2), NB1P(0, 2));

    // ---- layer 2 (final outputs) ----
    k_prep<<<NB, 256>>>(x, EW1P(0, 2), p_hl);
    k_edge<true, true, true><<<EGB, 256>>>(lrow, lcol, p_le, lattr, EW1P(0, 2), EW2P(0, 2), EB2P(0, 2), p_hl, p_le, outp);
    k_node<true><<<NB, 256>>>(x, p_cntl, NW1P(0, 2), NW2P(0, 2), NB2P(0, 2), EW1P(1, 2));
    k_global<<<1, 32>>>(GW(0, 2), EW1P(1, 2), EB1P(1, 2), NW1P(1, 2), NB1P(1, 2));
    k_edge<false, true, false><<<EGB, 256>>>(urow, ucol, p_ue, uattr, EW1P(1, 2), EW2P(1, 2), EB2P(1, 2), p_hu, p_ue,
                                             outp + E_EDGES);

#undef EW1P
#undef EB1P
#undef EW2P
#undef EB2P
#undef NW1P
#undef NB1P
#undef NW2P
#undef NB2P
#undef GW
}

// round 4
// speedup vs baseline: 1.3614x; 1.0684x over previous
#include <cuda_runtime.h>
#include <math.h>

#define N_NODES 100000
#define E_EDGES 1100000
#define HID 32
#define GF 8
#define NF 8

#define EBC ((E_EDGES + 255) / 256)   // 4297 count blocks
#define NPB ((N_NODES + 255) / 256)   // 391 per-node blocks

// ---------------- persistent device scratch ----------------
__device__ __align__(16) float d_hrc_l0[(size_t)N_NODES * 64];
__device__ __align__(16) float d_hrc_l1[(size_t)N_NODES * 64];
__device__ __align__(16) float d_hrc_l2[(size_t)N_NODES * 64];
__device__ __align__(16) float d_hrc_u[(size_t)N_NODES * 64];
__device__ __align__(16) float d_le[E_EDGES];
__device__ __align__(16) float d_ue[E_EDGES];
__device__ __align__(16) float d_ln[N_NODES * NF];
__device__ float d_agg[N_NODES];
__device__ float d_cntl[N_NODES];
__device__ float d_cntu[N_NODES];
__device__ float d_g[GF];
__device__ float d_nsum[GF];
__device__ float d_esum;
__device__ float d_hbase_e[HID];  // eb1 + g @ eW1[0:8]  (for the NEXT edge pass)
__device__ float d_hbase_n[HID];  // nb1 + g @ nW1[0:8]  (for the NEXT node pass)
__device__ unsigned d_ncnt;       // k_node completion counter

__inline__ __device__ float warpAllSum(float v) {
#pragma unroll
    for (int o = 16; o > 0; o >>= 1) v += __shfl_xor_sync(0xffffffffu, v, o);
    return v;
}

// ---------------- init ----------------
__global__ void k_zero(const float* __restrict__ eb1_0, const float* __restrict__ nb1_0) {
    int i = blockIdx.x * blockDim.x + threadIdx.x;
    if (i < N_NODES) {
        d_agg[i] = 0.f;
        d_cntl[i] = 0.f;
        d_cntu[i] = 0.f;
    }
    if (blockIdx.x == 0) {
        int j = threadIdx.x;
        if (j < HID) {  // g = 0 initially -> bases are just the biases
            d_hbase_e[j] = eb1_0[j];
            d_hbase_n[j] = nb1_0[j];
        }
        if (j < GF) { d_g[j] = 0.f; d_nsum[j] = 0.f; }
        if (j == 0) { d_esum = 0.f; d_ncnt = 0u; }
    }
}

// ---------------- prep body: hr = x @ W1[8:16], hc = x @ W1[16:24] ----------------
__device__ __forceinline__ void prep_body(int pb, int tid, float* sW,
                                          const float* __restrict__ xn,
                                          const float* __restrict__ W1,
                                          float* __restrict__ hrc) {
    for (int i = tid; i < 16 * HID; i += 256) sW[i] = W1[8 * HID + i];
    __syncthreads();

    int v = pb * 256 + tid;
    if (v >= N_NODES) return;
    const float4* xp = reinterpret_cast<const float4*>(xn + (size_t)v * 8);
    float4 x0 = xp[0], x1 = xp[1];
    float xv[8] = {x0.x, x0.y, x0.z, x0.w, x1.x, x1.y, x1.z, x1.w};

    float h[HID];
    float4* dst = reinterpret_cast<float4*>(hrc + (size_t)v * 64);
#pragma unroll
    for (int half = 0; half < 2; half++) {
#pragma unroll
        for (int j = 0; j < HID; j++) h[j] = 0.f;
#pragma unroll
        for (int k = 0; k < 8; k++) {
            float val = xv[k];
            const float4* wr = reinterpret_cast<const float4*>(&sW[(half * 8 + k) * HID]);
#pragma unroll
            for (int j4 = 0; j4 < HID / 4; j4++) {
                float4 w = wr[j4];
                h[j4 * 4 + 0] = fmaf(val, w.x, h[j4 * 4 + 0]);
                h[j4 * 4 + 1] = fmaf(val, w.y, h[j4 * 4 + 1]);
                h[j4 * 4 + 2] = fmaf(val, w.z, h[j4 * 4 + 2]);
                h[j4 * 4 + 3] = fmaf(val, w.w, h[j4 * 4 + 3]);
            }
        }
#pragma unroll
        for (int j4 = 0; j4 < HID / 4; j4++)
            dst[half * 8 + j4] = make_float4(h[j4 * 4], h[j4 * 4 + 1], h[j4 * 4 + 2], h[j4 * 4 + 3]);
    }
}

// ---------------- setup mega-kernel: edge counting + all 3 lower-layer tables ----------------
__global__ __launch_bounds__(256) void k_setup(const int* __restrict__ lrow,
                                               const int* __restrict__ urow,
                                               const float* __restrict__ x,
                                               const float* __restrict__ eW1_0,
                                               const float* __restrict__ eW1_1,
                                               const float* __restrict__ eW1_2) {
    __shared__ __align__(16) float sW[16 * HID];
    int bid = blockIdx.x;
    int tid = threadIdx.x;
    if (bid < EBC) {
        int e = bid * 256 + tid;
        if (e < E_EDGES) {
            atomicAdd(&d_cntl[lrow[e]], 1.0f);
            atomicAdd(&d_cntu[urow[e]], 1.0f);
        }
    } else {
        int t = bid - EBC;
        int layer = t / NPB;
        int pb = t % NPB;
        const float* W1 = (layer == 0) ? eW1_0 : (layer == 1) ? eW1_1 : eW1_2;
        float* hrc = (layer == 0) ? d_hrc_l0 : (layer == 1) ? d_hrc_l1 : d_hrc_l2;
        prep_body(pb, tid, sW, x, W1, hrc);
    }
}

// ---------------- edge kernel: 8 lanes/edge, 2 edges per group-iteration ----------------
template <bool HAS_SKIP, bool WRITE_OUT, bool DO_AGG>
__global__ __launch_bounds__(256) void k_edge(
    const int* __restrict__ row, const int* __restrict__ col,
    const float* __restrict__ eprev, const float* __restrict__ eskip,
    const float* __restrict__ W1,   // 26x32 (rows 24,25 used)
    const float* __restrict__ W2,   // 32
    const float* __restrict__ B2,   // 1
    const float* __restrict__ hrc,  // N x 64 table
    float* __restrict__ ebuf,
    float* __restrict__ outp) {
    __shared__ float sred[8];
    int tid = threadIdx.x;
    int c = tid & 7;   // owns h[c*4 .. c*4+3]
    int g = tid >> 3;  // edge-pair group within block (0..31)

    float base[4], w24[4], w25[4], w2[4];
#pragma unroll
    for (int i = 0; i < 4; i++) {
        base[i] = d_hbase_e[c * 4 + i];
        w24[i] = __ldg(&W1[24 * HID + c * 4 + i]);
        w25[i] = HAS_SKIP ? __ldg(&W1[25 * HID + c * 4 + i]) : 0.f;
        w2[i] = __ldg(&W2[c * 4 + i]);
    }
    float b2 = __ldg(B2);

    float esum_local = 0.f;
    const int step = gridDim.x * 64;
    // E_EDGES is even: e0 even implies e0+1 < E_EDGES whenever e0 < E_EDGES.
    for (int e0 = (blockIdx.x * 32 + g) * 2; e0 < E_EDGES; e0 += step) {
        int r0 = row[e0], r1 = row[e0 + 1];
        int c0 = col[e0], c1 = col[e0 + 1];
        float2 epv = *reinterpret_cast<const float2*>(&eprev[e0]);
        float2 esv = HAS_SKIP ? *reinterpret_cast<const float2*>(&eskip[e0]) : make_float2(0.f, 0.f);

        float4 hr0 = *reinterpret_cast<const float4*>(&hrc[(unsigned)r0 * 64 + c * 4]);
        float4 hc0 = *reinterpret_cast<const float4*>(&hrc[(unsigned)c0 * 64 + 32 + c * 4]);
        float4 hr1 = *reinterpret_cast<const float4*>(&hrc[(unsigned)r1 * 64 + c * 4]);
        float4 hc1 = *reinterpret_cast<const float4*>(&hrc[(unsigned)c1 * 64 + 32 + c * 4]);

        float p0 = 0.f, p1 = 0.f, t;
        t = base[0] + hr0.x + hc0.x; t = fmaf(epv.x, w24[0], t); if (HAS_SKIP) t = fmaf(esv.x, w25[0], t);
        p0 = fmaf(fmaxf(t, 0.f), w2[0], p0);
        t = base[0] + hr1.x + hc1.x; t = fmaf(epv.y, w24[0], t); if (HAS_SKIP) t = fmaf(esv.y, w25[0], t);
        p1 = fmaf(fmaxf(t, 0.f), w2[0], p1);
        t = base[1] + hr0.y + hc0.y; t = fmaf(epv.x, w24[1], t); if (HAS_SKIP) t = fmaf(esv.x, w25[1], t);
        p0 = fmaf(fmaxf(t, 0.f), w2[1], p0);
        t = base[1] + hr1.y + hc1.y; t = fmaf(epv.y, w24[1], t); if (HAS_SKIP) t = fmaf(esv.y, w25[1], t);
        p1 = fmaf(fmaxf(t, 0.f), w2[1], p1);
        t = base[2] + hr0.z + hc0.z; t = fmaf(epv.x, w24[2], t); if (HAS_SKIP) t = fmaf(esv.x, w25[2], t);
        p0 = fmaf(fmaxf(t, 0.f), w2[2], p0);
        t = base[2] + hr1.z + hc1.z; t = fmaf(epv.y, w24[2], t); if (HAS_SKIP) t = fmaf(esv.y, w25[2], t);
        p1 = fmaf(fmaxf(t, 0.f), w2[2], p1);
        t = base[3] + hr0.w + hc0.w; t = fmaf(epv.x, w24[3], t); if (HAS_SKIP) t = fmaf(esv.x, w25[3], t);
        p0 = fmaf(fmaxf(t, 0.f), w2[3], p0);
        t = base[3] + hr1.w + hc1.w; t = fmaf(epv.y, w24[3], t); if (HAS_SKIP) t = fmaf(esv.y, w25[3], t);
        p1 = fmaf(fmaxf(t, 0.f), w2[3], p1);

        // reduce across the 8 lanes of this group (both edges interleaved for ILP)
        p0 += __shfl_down_sync(0xffffffffu, p0, 4);
        p1 += __shfl_down_sync(0xffffffffu, p1, 4);
        p0 += __shfl_down_sync(0xffffffffu, p0, 2);
        p1 += __shfl_down_sync(0xffffffffu, p1, 2);
        p0 += __shfl_down_sync(0xffffffffu, p0, 1);
        p1 += __shfl_down_sync(0xffffffffu, p1, 1);
        if (c == 0) {
            float o0 = p0 + b2, o1 = p1 + b2;
            *reinterpret_cast<float2*>(&ebuf[e0]) = make_float2(o0, o1);
            if (DO_AGG) {
                atomicAdd(&d_agg[r0], o0);
                atomicAdd(&d_agg[r1], o1);
                esum_local += o0 + o1;
            }
            if (WRITE_OUT) {
                float q0 = (r0 == c0) ? expf(o0) : o0;
                float q1 = (r1 == c1) ? expf(o1) : o1;
                *reinterpret_cast<float2*>(&outp[e0]) = make_float2(q0, q1);
            }
        }
    }

    if (DO_AGG) {
        float s = warpAllSum(esum_local);
        if ((tid & 31) == 0) sred[tid >> 5] = s;
        __syncthreads();
        if (tid < 8) {
            float v = sred[tid];
            v += __shfl_xor_sync(0xffu, v, 1);
            v += __shfl_xor_sync(0xffu, v, 2);
            v += __shfl_xor_sync(0xffu, v, 4);
            if (tid == 0) atomicAdd(&d_esum, v);
        }
    }
}

// ---------------- node kernel + fused global update (last-block pattern) ----------------
template <bool FUSE_U>
__global__ __launch_bounds__(256) void k_node(
    const float* __restrict__ xn,   // N x 8 (x or ln)
    const float* __restrict__ cnt,  // N
    const float* __restrict__ W1,   // 17 x 32 (rows 8..16 used)
    const float* __restrict__ W2,   // 32 x 8
    const float* __restrict__ B2,   // 8
    const float* __restrict__ uW1,  // next (upper) edge W1, rows 8..24, used if FUSE_U
    // fused-global params: this pass's global MLP + next pass's layer-1 weights
    const float* __restrict__ gW1, const float* __restrict__ gB1,
    const float* __restrict__ gW2, const float* __restrict__ gB2,
    const float* __restrict__ neW1, const float* __restrict__ neB1,
    const float* __restrict__ nnW1, const float* __restrict__ nnB1) {
    __shared__ __align__(16) float sW1[9 * HID];
    __shared__ __align__(16) float sW2[HID * NF];
    __shared__ __align__(16) float sUW[16 * HID];
    __shared__ float sB2[NF];
    __shared__ float sbase[HID];
    __shared__ float sred[8][NF];
    __shared__ int s_last;

    int tid = threadIdx.x;
    for (int i = tid; i < 9 * HID; i += 256) sW1[i] = W1[8 * HID + i];
    for (int i = tid; i < HID * NF; i += 256) sW2[i] = W2[i];
    if (FUSE_U)
        for (int i = tid; i < 16 * HID; i += 256) sUW[i] = uW1[8 * HID + i];
    if (tid < HID) sbase[tid] = d_hbase_n[tid];
    if (tid < NF) sB2[tid] = B2[tid];
    __syncthreads();

    int v = blockIdx.x * 256 + tid;
    float o[NF];
#pragma unroll
    for (int f = 0; f < NF; f++) o[f] = 0.f;

    if (v < N_NODES) {
        const float4* xp = reinterpret_cast<const float4*>(xn + (size_t)v * 8);
        float4 x0 = xp[0], x1 = xp[1];
        float xv[8] = {x0.x, x0.y, x0.z, x0.w, x1.x, x1.y, x1.z, x1.w};
        float a = d_agg[v] / fmaxf(cnt[v], 1.0f);
        d_agg[v] = 0.f;  // recycle for next pass

        float h[HID];
#pragma unroll
        for (int j = 0; j < HID; j++) h[j] = sbase[j];
#pragma unroll
        for (int k = 0; k < 9; k++) {
            float val = (k < 8) ? xv[k] : a;
            const float4* wr = reinterpret_cast<const float4*>(&sW1[k * HID]);
#pragma unroll
            for (int j4 = 0; j4 < HID / 4; j4++) {
                float4 w = wr[j4];
                h[j4 * 4 + 0] = fmaf(val, w.x, h[j4 * 4 + 0]);
                h[j4 * 4 + 1] = fmaf(val, w.y, h[j4 * 4 + 1]);
                h[j4 * 4 + 2] = fmaf(val, w.z, h[j4 * 4 + 2]);
                h[j4 * 4 + 3] = fmaf(val, w.w, h[j4 * 4 + 3]);
            }
        }
#pragma unroll
        for (int f = 0; f < NF; f++) o[f] = sB2[f];
#pragma unroll
        for (int j = 0; j < HID; j++) {
            float r = fmaxf(h[j], 0.f);
            const float4* wr = reinterpret_cast<const float4*>(&sW2[j * NF]);
            float4 w0 = wr[0], w1 = wr[1];
            o[0] = fmaf(r, w0.x, o[0]); o[1] = fmaf(r, w0.y, o[1]);
            o[2] = fmaf(r, w0.z, o[2]); o[3] = fmaf(r, w0.w, o[3]);
            o[4] = fmaf(r, w1.x, o[4]); o[5] = fmaf(r, w1.y, o[5]);
            o[6] = fmaf(r, w1.z, o[6]); o[7] = fmaf(r, w1.w, o[7]);
        }

        if (FUSE_U) {
            float4* lnp = reinterpret_cast<float4*>(&d_ln[(size_t)v * 8]);
            lnp[0] = make_float4(o[0], o[1], o[2], o[3]);
            lnp[1] = make_float4(o[4], o[5], o[6], o[7]);
            float4* dst = reinterpret_cast<float4*>(&d_hrc_u[(size_t)v * 64]);
#pragma unroll
            for (int half = 0; half < 2; half++) {
                float t[HID];
#pragma unroll
                for (int j = 0; j < HID; j++) t[j] = 0.f;
#pragma unroll
                for (int k = 0; k < 8; k++) {
                    float val = o[k];
                    const float4* wr = reinterpret_cast<const float4*>(&sUW[(half * 8 + k) * HID]);
#pragma unroll
                    for (int j4 = 0; j4 < HID / 4; j4++) {
                        float4 w = wr[j4];
                        t[j4 * 4 + 0] = fmaf(val, w.x, t[j4 * 4 + 0]);
                        t[j4 * 4 + 1] = fmaf(val, w.y, t[j4 * 4 + 1]);
                        t[j4 * 4 + 2] = fmaf(val, w.z, t[j4 * 4 + 2]);
                        t[j4 * 4 + 3] = fmaf(val, w.w, t[j4 * 4 + 3]);
                    }
                }
#pragma unroll
                for (int j4 = 0; j4 < HID / 4; j4++)
                    dst[half * 8 + j4] = make_float4(t[j4 * 4], t[j4 * 4 + 1], t[j4 * 4 + 2], t[j4 * 4 + 3]);
            }
        }
    }

    // block-reduce node-embedding sums for the global mean
#pragma unroll
    for (int f = 0; f < NF; f++) {
        float s = warpAllSum(o[f]);
        if ((tid & 31) == 0) sred[tid >> 5][f] = s;
    }
    __syncthreads();
    if (tid < NF) {
        float s = 0.f;
#pragma unroll
        for (int w = 0; w < 8; w++) s += sred[w][tid];
        atomicAdd(&d_nsum[tid], s);
    }

    // ---- fused global update: last finishing block does the 1-row global MLP ----
    __syncthreads();
    if (tid == 0) {
        __threadfence();
        unsigned old = atomicAdd(&d_ncnt, 1u);
        s_last = (old == gridDim.x - 1) ? 1 : 0;
    }
    __syncthreads();
    if (s_last && tid < 32) {
        int j = tid;
        float in[17];
#pragma unroll
        for (int f = 0; f < NF; f++) in[f] = __ldcg(&d_nsum[f]) / (float)N_NODES;
        in[8] = __ldcg(&d_esum) / (float)E_EDGES;
#pragma unroll
        for (int f = 0; f < GF; f++) in[9 + f] = __ldcg(&d_g[f]);

        float h = gB1[j];
#pragma unroll
        for (int k = 0; k < 17; k++) h = fmaf(in[k], gW1[k * HID + j], h);
        h = fmaxf(h, 0.f);

        float gnew[GF];
#pragma unroll
        for (int f = 0; f < GF; f++) gnew[f] = __ldg(&gB2[f]) + warpAllSum(h * gW2[j * NF + f]);

        float be = neB1[j], bn = nnB1[j];
#pragma unroll
        for (int f = 0; f < GF; f++) {
            be = fmaf(gnew[f], neW1[f * HID + j], be);
            bn = fmaf(gnew[f], nnW1[f * HID + j], bn);
        }
        d_hbase_e[j] = be;
        d_hbase_n[j] = bn;

        if (j < GF) {
            d_g[j] = gnew[j];
            d_nsum[j] = 0.f;
        }
        if (j == 0) {
            d_esum = 0.f;
            d_ncnt = 0u;
        }
    }
}

// ---------------- host launch ----------------
extern "C" void kernel_launch(void* const* d_in, const int* in_sizes, int n_in,
                              void* d_out, int out_size) {
    const float* x = (const float*)d_in[0];
    const int* lei = (const int*)d_in[1];
    const int* uei = (const int*)d_in[2];
    const float* lattr = (const float*)d_in[3];
    const float* uattr = (const float*)d_in[4];
    const float* eW1 = (const float*)d_in[5];
    const float* eb1 = (const float*)d_in[6];
    const float* eW2 = (const float*)d_in[7];
    const float* eb2 = (const float*)d_in[8];
    const float* nW1 = (const float*)d_in[9];
    const float* nb1 = (const float*)d_in[10];
    const float* nW2 = (const float*)d_in[11];
    const float* nb2 = (const float*)d_in[12];
    const float* gW1 = (const float*)d_in[13];
    const float* gb1 = (const float*)d_in[14];
    const float* gW2 = (const float*)d_in[15];
    const float* gb2 = (const float*)d_in[16];
    float* outp = (float*)d_out;

    const int* lrow = lei;
    const int* lcol = lei + E_EDGES;
    const int* urow = uei;
    const int* ucol = uei + E_EDGES;

    float *p_le, *p_ue, *p_ln, *p_cntl, *p_cntu, *p_hl0, *p_hl1, *p_hl2, *p_hu;
    cudaGetSymbolAddress((void**)&p_le, d_le);
    cudaGetSymbolAddress((void**)&p_ue, d_ue);
    cudaGetSymbolAddress((void**)&p_ln, d_ln);
    cudaGetSymbolAddress((void**)&p_cntl, d_cntl);
    cudaGetSymbolAddress((void**)&p_cntu, d_cntu);
    cudaGetSymbolAddress((void**)&p_hl0, d_hrc_l0);
    cudaGetSymbolAddress((void**)&p_hl1, d_hrc_l1);
    cudaGetSymbolAddress((void**)&p_hl2, d_hrc_l2);
    cudaGetSymbolAddress((void**)&p_hu, d_hrc_u);
    float* p_hl[3] = {p_hl0, p_hl1, p_hl2};

    const int NB = NPB;
    const int EGB = 1184;  // grid-stride blocks for k_edge (8 per SM)

#define EW1P(b, i) (eW1 + (size_t)((b)*3 + (i)) * 26 * HID)
#define EB1P(b, i) (eb1 + ((b)*3 + (i)) * HID)
#define EW2P(b, i) (eW2 + ((b)*3 + (i)) * HID)
#define EB2P(b, i) (eb2 + ((b)*3 + (i)))
#define NW1P(b, i) (nW1 + (size_t)((b)*3 + (i)) * 17 * HID)
#define NB1P(b, i) (nb1 + ((b)*3 + (i)) * HID)
#define NW2P(b, i) (nW2 + (size_t)((b)*3 + (i)) * HID * NF)
#define NB2P(b, i) (nb2 + ((b)*3 + (i)) * NF)
#define GWP(b, i) gW1 + (size_t)((b)*3 + (i)) * 17 * HID, gb1 + ((b)*3 + (i)) * HID, \
                  gW2 + (size_t)((b)*3 + (i)) * HID * NF, gb2 + ((b)*3 + (i)) * NF

    k_zero<<<NB, 256>>>(EB1P(0, 0), NB1P(0, 0));
    k_setup<<<EBC + 3 * NPB, 256>>>(lrow, urow, x, EW1P(0, 0), EW1P(0, 1), EW1P(0, 2));

    for (int i = 0; i < 3; i++) {
        const float* le_prev = (i == 0) ? lattr : p_le;
        const float* ue_prev = (i == 0) ? uattr : p_ue;
        bool last = (i == 2);

        // lower edge pass (b=0)
        if (i == 0)
            k_edge<false, false, true><<<EGB, 256>>>(lrow, lcol, le_prev, lattr, EW1P(0, i), EW2P(0, i), EB2P(0, i), p_hl[i], p_le, outp);
        else if (!last)
            k_edge<true, false, true><<<EGB, 256>>>(lrow, lcol, le_prev, lattr, EW1P(0, i), EW2P(0, i), EB2P(0, i), p_hl[i], p_le, outp);
        else
            k_edge<true, true, true><<<EGB, 256>>>(lrow, lcol, le_prev, lattr, EW1P(0, i), EW2P(0, i), EB2P(0, i), p_hl[i], p_le, outp);

        // lower node pass + fused global (next pass = (1, i))
        k_node<true><<<NB, 256>>>(x, p_cntl, NW1P(0, i), NW2P(0, i), NB2P(0, i), EW1P(1, i),
                                  GWP(0, i), EW1P(1, i), EB1P(1, i), NW1P(1, i), NB1P(1, i));

        // upper edge pass (b=1)
        if (!last)
            k_edge<false, false, true><<<EGB, 256>>>(urow, ucol, ue_prev, uattr, EW1P(1, i), EW2P(1, i), EB2P(1, i), p_hu, p_ue, outp);
        else
            k_edge<false, true, false><<<EGB, 256>>>(urow, ucol, ue_prev, uattr, EW1P(1, i), EW2P(1, i), EB2P(1, i), p_hu, p_ue,
                                                     outp + E_EDGES);

        // upper node pass + fused global (next pass = (0, i+1)); skipped after final layer
        if (!last)
            k_node<false><<<NB, 256>>>(p_ln, p_cntu, NW1P(1, i), NW2P(1, i), NB2P(1, i), EW1P(1, i),
                                       GWP(1, i), EW1P(0, i + 1), EB1P(0, i + 1), NW1P(0, i + 1), NB1P(0, i + 1));
    }

#undef EW1P
#undef EB1P
#undef EW2P
#undef EB2P
#undef NW1P
#undef NB1P
#undef NW2P
#undef NB2P
#undef GWP
}